// round 9
// baseline (speedup 1.0000x reference)
#include <cuda_runtime.h>
#include <cuda_fp16.h>
#include <cstdint>

#define DIM 64
#define LMAX 200000
#define CMAX 80000
#define EMAX 1100000
#define SCAN_NB 256

// -------- scratch (static __device__ arrays; no allocation allowed) --------
__device__ float g_Ml2c[(size_t)LMAX * DIM];   // 51.2 MB
__device__ float g_Mc2l[(size_t)CMAX * DIM];   // 20.5 MB
__device__ float g_Ml2l[(size_t)LMAX * DIM];   // 51.2 MB
__device__ float g_aggrC[(size_t)CMAX * DIM];  // 20.5 MB
__device__ float g_aggrL[(size_t)LMAX * DIM];  // 51.2 MB
// CSR scratch
__device__ int g_cntC[CMAX],  g_rowC[CMAX + 1], g_curC[CMAX], g_srcC[EMAX];
__device__ int g_cntL[LMAX],  g_rowL[LMAX + 1], g_curL[LMAX], g_srcL[EMAX];
__device__ int g_bsumC[SCAN_NB], g_bsumL[SCAN_NB];

// ---------------------------------------------------------------------------
__device__ __forceinline__ uint32_t f2tf32(float f)
{
    uint32_t r;
    asm("cvt.rna.tf32.f32 %0, %1;" : "=r"(r) : "f"(f));
    return r;
}

__device__ __forceinline__ void mma_tf32(float* d, const uint32_t* a,
                                         uint32_t b0, uint32_t b1)
{
    asm volatile(
        "mma.sync.aligned.m16n8k8.row.col.f32.tf32.tf32.f32 "
        "{%0,%1,%2,%3}, {%4,%5,%6,%7}, {%8,%9}, {%0,%1,%2,%3};\n"
        : "+f"(d[0]), "+f"(d[1]), "+f"(d[2]), "+f"(d[3])
        : "r"(a[0]), "r"(a[1]), "r"(a[2]), "r"(a[3]), "r"(b0), "r"(b1));
}

// ---------------------------------------------------------------------------
// tf32 tensor-core fused 2-layer MLP: out = relu(X@W1+b1)@W2+b2
// Single-pass tf32 (per-op ~1.2e-4; measured network amplification ~1).
// X = concat of PARTS 64-wide row-blocks. FLIPOUT: result of row r written to
// row r^1 (== MLP of pair-flipped input; tiles are 64-aligned).
// Block: 128 threads = 4 warps; 64x64 tile; warp = 32x32 quadrant of m16n8k8.
// ---------------------------------------------------------------------------
template <int PARTS, bool FLIPOUT>
__global__ __launch_bounds__(128) void mlp_tc(
    const float* __restrict__ x0, const float* __restrict__ x1,
    const float* __restrict__ x2,
    const float* __restrict__ W1, const float* __restrict__ b1,
    const float* __restrict__ W2, const float* __restrict__ b2,
    float* __restrict__ out, int nrows)
{
    constexpr int K = PARTS * 64;
    constexpr int KS = K + 4;          // W1t row stride (n-major)
    extern __shared__ uint32_t smu[];
    uint32_t* W1t = smu;               // [64][KS]  W1t[n][k]
    uint32_t* W2t = W1t + 64 * KS;     // [64][68]  W2t[n][k]
    uint32_t* Xs  = W2t + 64 * 68;     // [64][68]  Xs[r][k]  (one 64-col chunk)
    uint32_t* Hs  = Xs + 64 * 68;      // [64][68]
    float* b1s = (float*)(Hs + 64 * 68);
    float* b2s = b1s + 64;

    const int tid = threadIdx.x;
    for (int i = tid; i < K * 64; i += 128) {
        int k = i >> 6, n = i & 63;
        W1t[n * KS + k] = f2tf32(W1[i]);
    }
    for (int i = tid; i < 64 * 64; i += 128) {
        int k = i >> 6, n = i & 63;
        W2t[n * 68 + k] = f2tf32(W2[i]);
    }
    if (tid < 64) { b1s[tid] = b1[tid]; b2s[tid] = b2[tid]; }
    __syncthreads();   // REQUIRED: acc-init below reads b1s/b2s across warps
                       // (missing barrier here was the R3/R4 correctness bug)

    const int lane = tid & 31;
    const int warp = tid >> 5;
    const int gid = lane >> 2, tig = lane & 3;
    const int wm = (warp & 1) * 32;    // warp row offset in tile
    const int wn = (warp >> 1) * 32;   // warp col offset

    const int ntiles = (nrows + 63) >> 6;
    for (int tile = blockIdx.x; tile < ntiles; tile += gridDim.x) {
        const int base = tile << 6;

        // ---- layer 1 accumulators, init with bias (exact fp32) ----
        float acc[2][4][4];
        #pragma unroll
        for (int nt = 0; nt < 4; ++nt) {
            float bv0 = b1s[wn + nt * 8 + 2 * tig];
            float bv1 = b1s[wn + nt * 8 + 2 * tig + 1];
            #pragma unroll
            for (int mt = 0; mt < 2; ++mt) {
                acc[mt][nt][0] = bv0; acc[mt][nt][1] = bv1;
                acc[mt][nt][2] = bv0; acc[mt][nt][3] = bv1;
            }
        }

        #pragma unroll
        for (int p = 0; p < PARTS; ++p) {
            const float* xp = (p == 0) ? x0 : ((p == 1) ? x1 : x2);
            __syncthreads();   // Xs/Hs free for reuse
            #pragma unroll 8
            for (int i = 0; i < 32; ++i) {
                int idx = tid + i * 128;
                int r = idx >> 6, k = idx & 63;
                int row = base + r;
                float v = (row < nrows) ? xp[(size_t)row * 64 + k] : 0.f;
                Xs[r * 68 + k] = f2tf32(v);
            }
            __syncthreads();

            #pragma unroll
            for (int ks = 0; ks < 8; ++ks) {
                const int k0 = ks * 8;
                uint32_t a[2][4];
                #pragma unroll
                for (int mt = 0; mt < 2; ++mt) {
                    int rb = wm + mt * 16;
                    a[mt][0] = Xs[(rb + gid) * 68 + k0 + tig];
                    a[mt][1] = Xs[(rb + gid + 8) * 68 + k0 + tig];
                    a[mt][2] = Xs[(rb + gid) * 68 + k0 + tig + 4];
                    a[mt][3] = Xs[(rb + gid + 8) * 68 + k0 + tig + 4];
                }
                const int kk = p * 64 + k0;
                #pragma unroll
                for (int nt = 0; nt < 4; ++nt) {
                    int n = wn + nt * 8 + gid;
                    uint32_t bv0 = W1t[n * KS + kk + tig];
                    uint32_t bv1 = W1t[n * KS + kk + tig + 4];
                    mma_tf32(acc[0][nt], a[0], bv0, bv1);
                    mma_tf32(acc[1][nt], a[1], bv0, bv1);
                }
            }
        }

        // ---- relu -> Hs (tf32) ----
        #pragma unroll
        for (int mt = 0; mt < 2; ++mt)
            #pragma unroll
            for (int nt = 0; nt < 4; ++nt) {
                int r0 = wm + mt * 16 + gid;
                int c0 = wn + nt * 8 + 2 * tig;
                Hs[r0 * 68 + c0]           = f2tf32(fmaxf(acc[mt][nt][0], 0.f));
                Hs[r0 * 68 + c0 + 1]       = f2tf32(fmaxf(acc[mt][nt][1], 0.f));
                Hs[(r0 + 8) * 68 + c0]     = f2tf32(fmaxf(acc[mt][nt][2], 0.f));
                Hs[(r0 + 8) * 68 + c0 + 1] = f2tf32(fmaxf(acc[mt][nt][3], 0.f));
            }
        __syncthreads();

        // ---- layer 2 ----
        float o[2][4][4];
        #pragma unroll
        for (int nt = 0; nt < 4; ++nt) {
            float bv0 = b2s[wn + nt * 8 + 2 * tig];
            float bv1 = b2s[wn + nt * 8 + 2 * tig + 1];
            #pragma unroll
            for (int mt = 0; mt < 2; ++mt) {
                o[mt][nt][0] = bv0; o[mt][nt][1] = bv1;
                o[mt][nt][2] = bv0; o[mt][nt][3] = bv1;
            }
        }
        #pragma unroll
        for (int ks = 0; ks < 8; ++ks) {
            const int k0 = ks * 8;
            uint32_t a[2][4];
            #pragma unroll
            for (int mt = 0; mt < 2; ++mt) {
                int rb = wm + mt * 16;
                a[mt][0] = Hs[(rb + gid) * 68 + k0 + tig];
                a[mt][1] = Hs[(rb + gid + 8) * 68 + k0 + tig];
                a[mt][2] = Hs[(rb + gid) * 68 + k0 + tig + 4];
                a[mt][3] = Hs[(rb + gid + 8) * 68 + k0 + tig + 4];
            }
            #pragma unroll
            for (int nt = 0; nt < 4; ++nt) {
                int n = wn + nt * 8 + gid;
                uint32_t bv0 = W2t[n * 68 + k0 + tig];
                uint32_t bv1 = W2t[n * 68 + k0 + tig + 4];
                mma_tf32(o[0][nt], a[0], bv0, bv1);
                mma_tf32(o[1][nt], a[1], bv0, bv1);
            }
        }

        // ---- epilogue: float2 stores (FLIPOUT writes row r^1) ----
        #pragma unroll
        for (int mt = 0; mt < 2; ++mt)
            #pragma unroll
            for (int nt = 0; nt < 4; ++nt) {
                int r = base + wm + mt * 16 + gid;
                int c = wn + nt * 8 + 2 * tig;
                if (r < nrows) {
                    int ro = FLIPOUT ? (r ^ 1) : r;
                    *(float2*)(out + (size_t)ro * 64 + c) =
                        make_float2(o[mt][nt][0], o[mt][nt][1]);
                }
                if (r + 8 < nrows) {
                    int ro = FLIPOUT ? ((r + 8) ^ 1) : (r + 8);
                    *(float2*)(out + (size_t)ro * 64 + c) =
                        make_float2(o[mt][nt][2], o[mt][nt][3]);
                }
            }
    }
}

// ---------------------------------------------------------------------------
// CSR build: count -> 3-kernel exclusive scan -> atomic placement
// ---------------------------------------------------------------------------
__global__ void count_kernel(const int* __restrict__ dest, int E, int* __restrict__ cnt)
{
    int e = blockIdx.x * 256 + threadIdx.x;
    if (e < E) atomicAdd(&cnt[dest[e]], 1);
}

__global__ void scan_reduce(const int* __restrict__ cnt, int n, int* __restrict__ bsum)
{
    int b = blockIdx.x;
    int CH = (n + SCAN_NB - 1) / SCAN_NB;
    int s = b * CH, e = min(n, s + CH);
    __shared__ int sh[256];
    int t = threadIdx.x, sum = 0;
    for (int i = s + t; i < e; i += 256) sum += cnt[i];
    sh[t] = sum; __syncthreads();
    for (int o = 128; o > 0; o >>= 1) {
        if (t < o) sh[t] += sh[t + o];
        __syncthreads();
    }
    if (t == 0) bsum[b] = sh[0];
}

__global__ void scan_bsum(int* __restrict__ bsum)
{
    __shared__ int sh[256];
    int t = threadIdx.x;
    sh[t] = bsum[t]; __syncthreads();
    for (int o = 1; o < 256; o <<= 1) {
        int v = (t >= o) ? sh[t - o] : 0;
        __syncthreads();
        sh[t] += v;
        __syncthreads();
    }
    bsum[t] = (t == 0) ? 0 : sh[t - 1];
}

__global__ void scan_write(const int* __restrict__ cnt, int n,
                           const int* __restrict__ bsum, int* __restrict__ rowptr, int total)
{
    int b = blockIdx.x;
    int CH = (n + SCAN_NB - 1) / SCAN_NB;
    int s = b * CH, e = min(n, s + CH);
    int t = threadIdx.x;
    int per = (CH + 255) / 256;
    int ts = min(e, s + t * per), te = min(e, s + t * per + per);
    int sum = 0;
    for (int i = ts; i < te; ++i) sum += cnt[i];
    __shared__ int sh[256];
    sh[t] = sum; __syncthreads();
    for (int o = 1; o < 256; o <<= 1) {
        int v = (t >= o) ? sh[t - o] : 0;
        __syncthreads();
        sh[t] += v;
        __syncthreads();
    }
    int off = bsum[b] + ((t == 0) ? 0 : sh[t - 1]);
    for (int i = ts; i < te; ++i) { rowptr[i] = off; off += cnt[i]; }
    if (b == 0 && t == 0) rowptr[n] = total;
}

__global__ void place_kernel(const int* __restrict__ dest, const int* __restrict__ srcn,
                             int E, int* __restrict__ cursor, int* __restrict__ srcidx)
{
    int e = blockIdx.x * 256 + threadIdx.x;
    if (e < E) {
        int p = atomicAdd(&cursor[dest[e]], 1);
        srcidx[p] = srcn[e];
    }
}

// ---------------------------------------------------------------------------
// Gather aggregation: dst[d] = sum over CSR row d of src[srcidx[i]]  (64 floats)
// Half-warp (16 lanes) per destination; each lane owns one float4 column.
// ---------------------------------------------------------------------------
__global__ __launch_bounds__(256) void gather_kernel(
    const float* __restrict__ src, const int* __restrict__ srcidx,
    const int* __restrict__ rowptr, float* __restrict__ dst, int n)
{
    int d = blockIdx.x * 16 + (threadIdx.x >> 4);
    int q = threadIdx.x & 15;
    if (d >= n) return;
    int s = rowptr[d], e = rowptr[d + 1];
    float ax = 0.f, ay = 0.f, az = 0.f, aw = 0.f;
    for (int i = s; i < e; ++i) {
        int r = __ldg(srcidx + i);
        float4 v = *(const float4*)(src + (size_t)r * 64 + q * 4);
        ax += v.x; ay += v.y; az += v.z; aw += v.w;
    }
    *(float4*)(dst + (size_t)d * 64 + q * 4) = make_float4(ax, ay, az, aw);
}

// ---------------------------------------------------------------------------
static inline size_t mlp_smem_bytes(int parts)
{
    int KS = parts * 64 + 4;
    return (size_t)(64 * KS + 3 * 64 * 68 + 128) * sizeof(uint32_t);
}

extern "C" void kernel_launch(void* const* d_in, const int* in_sizes, int n_in,
                              void* d_out, int out_size)
{
    const int off = n_in - 24;
    const int* l_edge = (const int*)d_in[off + 0];
    const int* c_edge = (const int*)d_in[off + 1];
    const float* l_emb_in = (const float*)d_in[off + 2];
    const float* c_emb_in = (const float*)d_in[off + 3];
    const int E = in_sizes[off + 0];
    const int L = in_sizes[off + 2] / DIM;
    const int C = in_sizes[off + 3] / DIM;

    const float* W[5][4];
    for (int m = 0; m < 5; ++m)
        for (int j = 0; j < 4; ++j)
            W[m][j] = (const float*)d_in[off + 4 + m * 4 + j];

    float* Ml2c, * Mc2l, * Ml2l, * aggrC, * aggrL;
    int *cntC, *rowC, *curC, *srcC, *bsC;
    int *cntL, *rowL, *curL, *srcL, *bsL;
    cudaGetSymbolAddress((void**)&Ml2c, g_Ml2c);
    cudaGetSymbolAddress((void**)&Mc2l, g_Mc2l);
    cudaGetSymbolAddress((void**)&Ml2l, g_Ml2l);
    cudaGetSymbolAddress((void**)&aggrC, g_aggrC);
    cudaGetSymbolAddress((void**)&aggrL, g_aggrL);
    cudaGetSymbolAddress((void**)&cntC, g_cntC);
    cudaGetSymbolAddress((void**)&rowC, g_rowC);
    cudaGetSymbolAddress((void**)&curC, g_curC);
    cudaGetSymbolAddress((void**)&srcC, g_srcC);
    cudaGetSymbolAddress((void**)&bsC,  g_bsumC);
    cudaGetSymbolAddress((void**)&cntL, g_cntL);
    cudaGetSymbolAddress((void**)&rowL, g_rowL);
    cudaGetSymbolAddress((void**)&curL, g_curL);
    cudaGetSymbolAddress((void**)&srcL, g_srcL);
    cudaGetSymbolAddress((void**)&bsL,  g_bsumL);

    const size_t sm1 = mlp_smem_bytes(1);
    const size_t sm2 = mlp_smem_bytes(2);
    const size_t sm3 = mlp_smem_bytes(3);
    cudaFuncSetAttribute(mlp_tc<1, false>, cudaFuncAttributeMaxDynamicSharedMemorySize, (int)sm1);
    cudaFuncSetAttribute(mlp_tc<1, true>,  cudaFuncAttributeMaxDynamicSharedMemorySize, (int)sm1);
    cudaFuncSetAttribute(mlp_tc<2, false>, cudaFuncAttributeMaxDynamicSharedMemorySize, (int)sm2);
    cudaFuncSetAttribute(mlp_tc<3, false>, cudaFuncAttributeMaxDynamicSharedMemorySize, (int)sm3);

    float* outBase = (float*)d_out;
    float* outL = outBase;                          // (3, L, 64)
    float* outC = outBase + (size_t)3 * L * DIM;    // (3, C, 64)

    cudaMemcpyAsync(outL, l_emb_in, (size_t)L * DIM * sizeof(float), cudaMemcpyDeviceToDevice);
    cudaMemcpyAsync(outC, c_emb_in, (size_t)C * DIM * sizeof(float), cudaMemcpyDeviceToDevice);

    // ---- CSR build (edges are iteration-invariant; amortized over 4 gathers) ----
    const int eb = (E + 255) / 256;
    cudaMemsetAsync(cntC, 0, C * sizeof(int));
    count_kernel<<<eb, 256>>>(c_edge, E, cntC);
    scan_reduce<<<SCAN_NB, 256>>>(cntC, C, bsC);
    scan_bsum<<<1, 256>>>(bsC);
    scan_write<<<SCAN_NB, 256>>>(cntC, C, bsC, rowC, E);
    cudaMemcpyAsync(curC, rowC, C * sizeof(int), cudaMemcpyDeviceToDevice);
    place_kernel<<<eb, 256>>>(c_edge, l_edge, E, curC, srcC);
    cudaMemsetAsync(cntL, 0, L * sizeof(int));
    count_kernel<<<eb, 256>>>(l_edge, E, cntL);
    scan_reduce<<<SCAN_NB, 256>>>(cntL, L, bsL);
    scan_bsum<<<1, 256>>>(bsL);
    scan_write<<<SCAN_NB, 256>>>(cntL, L, bsL, rowL, E);
    cudaMemcpyAsync(curL, rowL, L * sizeof(int), cudaMemcpyDeviceToDevice);
    place_kernel<<<eb, 256>>>(l_edge, c_edge, E, curL, srcL);

    const int ltiles = (L + 63) >> 6;
    const int ctiles = (C + 63) >> 6;
    auto gridFor = [](int tiles, int maxResident) {
        return tiles < maxResident ? tiles : maxResident;
    };
    const int g1L = gridFor(ltiles, 148 * 3);   // parts=1: ~70KB smem -> 3 blocks/SM
    const int g1C = gridFor(ctiles, 148 * 3);
    const int g2C = gridFor(ctiles, 148 * 2);   // parts=2: ~87KB -> 2 blocks/SM
    const int g3L = gridFor(ltiles, 148 * 2);   // parts=3: ~103KB -> 2 blocks/SM

    for (int t = 0; t < 2; ++t) {
        const float* le = outL + (size_t)t * L * DIM;
        const float* ce = outC + (size_t)t * C * DIM;
        float* nle = outL + (size_t)(t + 1) * L * DIM;
        float* nce = outC + (size_t)(t + 1) * C * DIM;

        // messages (from OLD embeddings)
        mlp_tc<1, false><<<g1L, 128, sm1>>>(le, nullptr, nullptr,
            W[0][0], W[0][1], W[0][2], W[0][3], Ml2c, L);
        mlp_tc<1, false><<<g1C, 128, sm1>>>(ce, nullptr, nullptr,
            W[1][0], W[1][1], W[1][2], W[1][3], Mc2l, C);
        mlp_tc<1, true><<<g1L, 128, sm1>>>(le, nullptr, nullptr,
            W[2][0], W[2][1], W[2][2], W[2][3], Ml2l, L);

        // aggregation via gather (no atomics, no memsets)
        gather_kernel<<<(C + 15) / 16, 256>>>(Ml2c, srcC, rowC, aggrC, C);
        gather_kernel<<<(L + 15) / 16, 256>>>(Mc2l, srcL, rowL, aggrL, L);

        // updates
        mlp_tc<2, false><<<g2C, 128, sm2>>>(ce, aggrC, nullptr,
            W[3][0], W[3][1], W[3][2], W[3][3], nce, C);
        mlp_tc<3, false><<<g3L, 128, sm3>>>(le, aggrL, Ml2l,
            W[4][0], W[4][1], W[4][2], W[4][3], nle, L);
    }
    (void)out_size;
}

// round 10
// speedup vs baseline: 1.2440x; 1.2440x over previous
#include <cuda_runtime.h>
#include <cuda_fp16.h>
#include <cstdint>

#define DIM 64
#define LMAX 200000
#define CMAX 80000
#define EMAX 1100000
#define SCAN_NB 256

// -------- scratch (static __device__ arrays; no allocation allowed) --------
__device__ float g_Ml2c[(size_t)LMAX * DIM];   // 51.2 MB
__device__ float g_Mc2l[(size_t)CMAX * DIM];   // 20.5 MB
__device__ float g_Ml2l[(size_t)LMAX * DIM];   // 51.2 MB
__device__ float g_aggrC[(size_t)CMAX * DIM];  // 20.5 MB
__device__ float g_aggrL[(size_t)LMAX * DIM];  // 51.2 MB
// CSR scratch
__device__ int g_cntC[CMAX],  g_rowC[CMAX + 1], g_curC[CMAX], g_srcC[EMAX];
__device__ int g_cntL[LMAX],  g_rowL[LMAX + 1], g_curL[LMAX], g_srcL[EMAX];
__device__ int g_bsumC[SCAN_NB], g_bsumL[SCAN_NB];

// ---------------------------------------------------------------------------
__device__ __forceinline__ void mma_16816(float* d, const uint32_t* a,
                                          const uint32_t* b)
{
    asm volatile(
        "mma.sync.aligned.m16n8k16.row.col.f32.f16.f16.f32 "
        "{%0,%1,%2,%3}, {%4,%5,%6,%7}, {%8,%9}, {%0,%1,%2,%3};\n"
        : "+f"(d[0]), "+f"(d[1]), "+f"(d[2]), "+f"(d[3])
        : "r"(a[0]), "r"(a[1]), "r"(a[2]), "r"(a[3]), "r"(b[0]), "r"(b[1]));
}

// ---------------------------------------------------------------------------
// 2-term fp16-split tensor-core fused 2-layer MLP: out = relu(X@W1+b1)@W2+b2
// Weights are hi+lo fp16 (exact to ~2^-22); activations single fp16 (one
// rounding at 2^-11 per GEMM -> half the rounding sources of tf32, which
// measured 1.78e-4 end-to-end). GEMM = Xh*Wh + Xh*Wl, fp32 accumulate.
// X = concat of PARTS 64-wide row-blocks. FLIPOUT: row r result -> row r^1.
// Block: 128 threads = 4 warps; 64x64 tile; warp = 32x32 quadrant, m16n8k16.
// ---------------------------------------------------------------------------
template <int PARTS, bool FLIPOUT>
__global__ __launch_bounds__(128) void mlp_tc(
    const float* __restrict__ x0, const float* __restrict__ x1,
    const float* __restrict__ x2,
    const float* __restrict__ W1, const float* __restrict__ b1,
    const float* __restrict__ W2, const float* __restrict__ b2,
    float* __restrict__ out, int nrows)
{
    constexpr int K  = PARTS * 64;
    constexpr int WS = K + 8;   // W1 row stride in halves (word-stride == 4 mod 32)
    constexpr int XS = 72;      // X/H/W2 row stride in halves

    extern __shared__ __half smh[];
    __half* W1h = smh;                 // [64][WS]  (n-major: W1h[n][k])
    __half* W1l = W1h + 64 * WS;
    __half* W2h = W1l + 64 * WS;       // [64][XS]
    __half* W2l = W2h + 64 * XS;
    __half* Xh  = W2l + 64 * XS;       // [64][XS]  one 64-col chunk of X (hi only)
    __half* Hh  = Xh + 64 * XS;        // [64][XS]  (hi only)
    float*  b1s = (float*)(Hh + 64 * XS);
    float*  b2s = b1s + 64;

    const int tid = threadIdx.x;
    // stage weights transposed (n-major), hi/lo split
    for (int i = tid; i < K * 64; i += 128) {
        int k = i >> 6, n = i & 63;
        float w = W1[i];
        __half hi = __float2half_rn(w);
        W1h[n * WS + k] = hi;
        W1l[n * WS + k] = __float2half_rn(w - __half2float(hi));
    }
    for (int i = tid; i < 64 * 64; i += 128) {
        int k = i >> 6, n = i & 63;
        float w = W2[i];
        __half hi = __float2half_rn(w);
        W2h[n * XS + k] = hi;
        W2l[n * XS + k] = __float2half_rn(w - __half2float(hi));
    }
    if (tid < 64) { b1s[tid] = b1[tid]; b2s[tid] = b2[tid]; }
    __syncthreads();   // REQUIRED: acc-init below reads b1s/b2s across warps
                       // (missing barrier here was the R3/R4 correctness bug)

    const int lane = tid & 31;
    const int warp = tid >> 5;
    const int gid = lane >> 2, tig = lane & 3;
    const int wm = (warp & 1) * 32;    // warp row offset in 64x64 tile
    const int wn = (warp >> 1) * 32;   // warp col offset

    const int ntiles = (nrows + 63) >> 6;
    for (int tile = blockIdx.x; tile < ntiles; tile += gridDim.x) {
        const int base = tile << 6;

        // ---- layer-1 accumulators, init with bias (exact fp32) ----
        float acc[2][4][4];
        #pragma unroll
        for (int nt = 0; nt < 4; ++nt) {
            float bv0 = b1s[wn + nt * 8 + 2 * tig];
            float bv1 = b1s[wn + nt * 8 + 2 * tig + 1];
            #pragma unroll
            for (int mt = 0; mt < 2; ++mt) {
                acc[mt][nt][0] = bv0; acc[mt][nt][1] = bv1;
                acc[mt][nt][2] = bv0; acc[mt][nt][3] = bv1;
            }
        }

        #pragma unroll
        for (int p = 0; p < PARTS; ++p) {
            const float* xp = (p == 0) ? x0 : ((p == 1) ? x1 : x2);
            __syncthreads();   // Xh/Hh free for reuse (prev part / prev tile done)
            #pragma unroll
            for (int i = 0; i < 16; ++i) {
                int idx = tid + i * 128;       // 2048 half2-pairs
                int r = idx >> 5, kp = idx & 31;
                int row = base + r;
                float2 v = make_float2(0.f, 0.f);
                if (row < nrows) v = *(const float2*)(xp + (size_t)row * 64 + 2 * kp);
                *(__half2*)(Xh + r * XS + 2 * kp) = __floats2half2_rn(v.x, v.y);
            }
            __syncthreads();

            #pragma unroll
            for (int kb = 0; kb < 4; ++kb) {
                const int k0 = kb * 16;
                uint32_t ah[2][4];
                #pragma unroll
                for (int mt = 0; mt < 2; ++mt) {
                    int r0 = (wm + mt * 16 + gid) * XS;
                    int r8 = r0 + 8 * XS;
                    ah[mt][0] = *(const uint32_t*)(Xh + r0 + k0 + 2 * tig);
                    ah[mt][1] = *(const uint32_t*)(Xh + r8 + k0 + 2 * tig);
                    ah[mt][2] = *(const uint32_t*)(Xh + r0 + k0 + 2 * tig + 8);
                    ah[mt][3] = *(const uint32_t*)(Xh + r8 + k0 + 2 * tig + 8);
                }
                const int kk = p * 64 + k0;
                uint32_t bh[4][2], bl[4][2];
                #pragma unroll
                for (int nt = 0; nt < 4; ++nt) {
                    int n = (wn + nt * 8 + gid) * WS;
                    bh[nt][0] = *(const uint32_t*)(W1h + n + kk + 2 * tig);
                    bh[nt][1] = *(const uint32_t*)(W1h + n + kk + 2 * tig + 8);
                    bl[nt][0] = *(const uint32_t*)(W1l + n + kk + 2 * tig);
                    bl[nt][1] = *(const uint32_t*)(W1l + n + kk + 2 * tig + 8);
                }
                #pragma unroll
                for (int nt = 0; nt < 4; ++nt) {
                    mma_16816(acc[0][nt], ah[0], bh[nt]);
                    mma_16816(acc[1][nt], ah[1], bh[nt]);
                }
                #pragma unroll
                for (int nt = 0; nt < 4; ++nt) {
                    mma_16816(acc[0][nt], ah[0], bl[nt]);
                    mma_16816(acc[1][nt], ah[1], bl[nt]);
                }
            }
        }

        // ---- relu -> Hh (fp16 hi only; the single A-side rounding) ----
        #pragma unroll
        for (int mt = 0; mt < 2; ++mt)
            #pragma unroll
            for (int nt = 0; nt < 4; ++nt) {
                int r0 = wm + mt * 16 + gid;
                int c0 = wn + nt * 8 + 2 * tig;
                *(__half2*)(Hh + r0 * XS + c0) =
                    __floats2half2_rn(fmaxf(acc[mt][nt][0], 0.f),
                                      fmaxf(acc[mt][nt][1], 0.f));
                *(__half2*)(Hh + (r0 + 8) * XS + c0) =
                    __floats2half2_rn(fmaxf(acc[mt][nt][2], 0.f),
                                      fmaxf(acc[mt][nt][3], 0.f));
            }
        __syncthreads();

        // ---- layer 2 ----
        float o[2][4][4];
        #pragma unroll
        for (int nt = 0; nt < 4; ++nt) {
            float bv0 = b2s[wn + nt * 8 + 2 * tig];
            float bv1 = b2s[wn + nt * 8 + 2 * tig + 1];
            #pragma unroll
            for (int mt = 0; mt < 2; ++mt) {
                o[mt][nt][0] = bv0; o[mt][nt][1] = bv1;
                o[mt][nt][2] = bv0; o[mt][nt][3] = bv1;
            }
        }
        #pragma unroll
        for (int kb = 0; kb < 4; ++kb) {
            const int k0 = kb * 16;
            uint32_t ah[2][4];
            #pragma unroll
            for (int mt = 0; mt < 2; ++mt) {
                int r0 = (wm + mt * 16 + gid) * XS;
                int r8 = r0 + 8 * XS;
                ah[mt][0] = *(const uint32_t*)(Hh + r0 + k0 + 2 * tig);
                ah[mt][1] = *(const uint32_t*)(Hh + r8 + k0 + 2 * tig);
                ah[mt][2] = *(const uint32_t*)(Hh + r0 + k0 + 2 * tig + 8);
                ah[mt][3] = *(const uint32_t*)(Hh + r8 + k0 + 2 * tig + 8);
            }
            uint32_t bh[4][2], bl[4][2];
            #pragma unroll
            for (int nt = 0; nt < 4; ++nt) {
                int n = (wn + nt * 8 + gid) * XS;
                bh[nt][0] = *(const uint32_t*)(W2h + n + k0 + 2 * tig);
                bh[nt][1] = *(const uint32_t*)(W2h + n + k0 + 2 * tig + 8);
                bl[nt][0] = *(const uint32_t*)(W2l + n + k0 + 2 * tig);
                bl[nt][1] = *(const uint32_t*)(W2l + n + k0 + 2 * tig + 8);
            }
            #pragma unroll
            for (int nt = 0; nt < 4; ++nt) {
                mma_16816(o[0][nt], ah[0], bh[nt]);
                mma_16816(o[1][nt], ah[1], bh[nt]);
            }
            #pragma unroll
            for (int nt = 0; nt < 4; ++nt) {
                mma_16816(o[0][nt], ah[0], bl[nt]);
                mma_16816(o[1][nt], ah[1], bl[nt]);
            }
        }

        // ---- epilogue: float2 stores (FLIPOUT writes row r^1) ----
        #pragma unroll
        for (int mt = 0; mt < 2; ++mt)
            #pragma unroll
            for (int nt = 0; nt < 4; ++nt) {
                int r = base + wm + mt * 16 + gid;
                int c = wn + nt * 8 + 2 * tig;
                if (r < nrows) {
                    int ro = FLIPOUT ? (r ^ 1) : r;
                    *(float2*)(out + (size_t)ro * 64 + c) =
                        make_float2(o[mt][nt][0], o[mt][nt][1]);
                }
                if (r + 8 < nrows) {
                    int ro = FLIPOUT ? ((r + 8) ^ 1) : (r + 8);
                    *(float2*)(out + (size_t)ro * 64 + c) =
                        make_float2(o[mt][nt][2], o[mt][nt][3]);
                }
            }
    }
}

// ---------------------------------------------------------------------------
// CSR build: count -> 3-kernel exclusive scan -> atomic placement
// ---------------------------------------------------------------------------
__global__ void count_kernel(const int* __restrict__ dest, int E, int* __restrict__ cnt)
{
    int e = blockIdx.x * 256 + threadIdx.x;
    if (e < E) atomicAdd(&cnt[dest[e]], 1);
}

__global__ void scan_reduce(const int* __restrict__ cnt, int n, int* __restrict__ bsum)
{
    int b = blockIdx.x;
    int CH = (n + SCAN_NB - 1) / SCAN_NB;
    int s = b * CH, e = min(n, s + CH);
    __shared__ int sh[256];
    int t = threadIdx.x, sum = 0;
    for (int i = s + t; i < e; i += 256) sum += cnt[i];
    sh[t] = sum; __syncthreads();
    for (int o = 128; o > 0; o >>= 1) {
        if (t < o) sh[t] += sh[t + o];
        __syncthreads();
    }
    if (t == 0) bsum[b] = sh[0];
}

__global__ void scan_bsum(int* __restrict__ bsum)
{
    __shared__ int sh[256];
    int t = threadIdx.x;
    sh[t] = bsum[t]; __syncthreads();
    for (int o = 1; o < 256; o <<= 1) {
        int v = (t >= o) ? sh[t - o] : 0;
        __syncthreads();
        sh[t] += v;
        __syncthreads();
    }
    bsum[t] = (t == 0) ? 0 : sh[t - 1];
}

__global__ void scan_write(const int* __restrict__ cnt, int n,
                           const int* __restrict__ bsum, int* __restrict__ rowptr, int total)
{
    int b = blockIdx.x;
    int CH = (n + SCAN_NB - 1) / SCAN_NB;
    int s = b * CH, e = min(n, s + CH);
    int t = threadIdx.x;
    int per = (CH + 255) / 256;
    int ts = min(e, s + t * per), te = min(e, s + t * per + per);
    int sum = 0;
    for (int i = ts; i < te; ++i) sum += cnt[i];
    __shared__ int sh[256];
    sh[t] = sum; __syncthreads();
    for (int o = 1; o < 256; o <<= 1) {
        int v = (t >= o) ? sh[t - o] : 0;
        __syncthreads();
        sh[t] += v;
        __syncthreads();
    }
    int off = bsum[b] + ((t == 0) ? 0 : sh[t - 1]);
    for (int i = ts; i < te; ++i) { rowptr[i] = off; off += cnt[i]; }
    if (b == 0 && t == 0) rowptr[n] = total;
}

__global__ void place_kernel(const int* __restrict__ dest, const int* __restrict__ srcn,
                             int E, int* __restrict__ cursor, int* __restrict__ srcidx)
{
    int e = blockIdx.x * 256 + threadIdx.x;
    if (e < E) {
        int p = atomicAdd(&cursor[dest[e]], 1);
        srcidx[p] = srcn[e];
    }
}

// ---------------------------------------------------------------------------
// Gather aggregation: dst[d] = sum over CSR row d of src[srcidx[i]]  (64 floats)
// Half-warp (16 lanes) per destination; each lane owns one float4 column.
// ---------------------------------------------------------------------------
__global__ __launch_bounds__(256) void gather_kernel(
    const float* __restrict__ src, const int* __restrict__ srcidx,
    const int* __restrict__ rowptr, float* __restrict__ dst, int n)
{
    int d = blockIdx.x * 16 + (threadIdx.x >> 4);
    int q = threadIdx.x & 15;
    if (d >= n) return;
    int s = rowptr[d], e = rowptr[d + 1];
    float ax = 0.f, ay = 0.f, az = 0.f, aw = 0.f;
    for (int i = s; i < e; ++i) {
        int r = __ldg(srcidx + i);
        float4 v = *(const float4*)(src + (size_t)r * 64 + q * 4);
        ax += v.x; ay += v.y; az += v.z; aw += v.w;
    }
    *(float4*)(dst + (size_t)d * 64 + q * 4) = make_float4(ax, ay, az, aw);
}

// ---------------------------------------------------------------------------
static inline size_t mlp_smem_bytes(int parts)
{
    int WS = parts * 64 + 8;
    size_t halves = (size_t)2 * 64 * WS + (size_t)4 * 64 * 72;
    return halves * 2 + 128 * sizeof(float);
}

extern "C" void kernel_launch(void* const* d_in, const int* in_sizes, int n_in,
                              void* d_out, int out_size)
{
    const int off = n_in - 24;
    const int* l_edge = (const int*)d_in[off + 0];
    const int* c_edge = (const int*)d_in[off + 1];
    const float* l_emb_in = (const float*)d_in[off + 2];
    const float* c_emb_in = (const float*)d_in[off + 3];
    const int E = in_sizes[off + 0];
    const int L = in_sizes[off + 2] / DIM;
    const int C = in_sizes[off + 3] / DIM;

    const float* W[5][4];
    for (int m = 0; m < 5; ++m)
        for (int j = 0; j < 4; ++j)
            W[m][j] = (const float*)d_in[off + 4 + m * 4 + j];
    // m: 0=l2c, 1=c2l, 2=l2l, 3=cu, 4=lu

    float* Ml2c, * Mc2l, * Ml2l, * aggrC, * aggrL;
    int *cntC, *rowC, *curC, *srcC, *bsC;
    int *cntL, *rowL, *curL, *srcL, *bsL;
    cudaGetSymbolAddress((void**)&Ml2c, g_Ml2c);
    cudaGetSymbolAddress((void**)&Mc2l, g_Mc2l);
    cudaGetSymbolAddress((void**)&Ml2l, g_Ml2l);
    cudaGetSymbolAddress((void**)&aggrC, g_aggrC);
    cudaGetSymbolAddress((void**)&aggrL, g_aggrL);
    cudaGetSymbolAddress((void**)&cntC, g_cntC);
    cudaGetSymbolAddress((void**)&rowC, g_rowC);
    cudaGetSymbolAddress((void**)&curC, g_curC);
    cudaGetSymbolAddress((void**)&srcC, g_srcC);
    cudaGetSymbolAddress((void**)&bsC,  g_bsumC);
    cudaGetSymbolAddress((void**)&cntL, g_cntL);
    cudaGetSymbolAddress((void**)&rowL, g_rowL);
    cudaGetSymbolAddress((void**)&curL, g_curL);
    cudaGetSymbolAddress((void**)&srcL, g_srcL);
    cudaGetSymbolAddress((void**)&bsL,  g_bsumL);

    const size_t sm1 = mlp_smem_bytes(1);
    const size_t sm2 = mlp_smem_bytes(2);
    const size_t sm3 = mlp_smem_bytes(3);
    cudaFuncSetAttribute(mlp_tc<1, false>, cudaFuncAttributeMaxDynamicSharedMemorySize, (int)sm1);
    cudaFuncSetAttribute(mlp_tc<1, true>,  cudaFuncAttributeMaxDynamicSharedMemorySize, (int)sm1);
    cudaFuncSetAttribute(mlp_tc<2, false>, cudaFuncAttributeMaxDynamicSharedMemorySize, (int)sm2);
    cudaFuncSetAttribute(mlp_tc<3, false>, cudaFuncAttributeMaxDynamicSharedMemorySize, (int)sm3);

    float* outBase = (float*)d_out;
    float* outL = outBase;                          // (3, L, 64)
    float* outC = outBase + (size_t)3 * L * DIM;    // (3, C, 64)

    cudaMemcpyAsync(outL, l_emb_in, (size_t)L * DIM * sizeof(float), cudaMemcpyDeviceToDevice);
    cudaMemcpyAsync(outC, c_emb_in, (size_t)C * DIM * sizeof(float), cudaMemcpyDeviceToDevice);

    // ---- CSR build (edges are iteration-invariant; amortized over 4 gathers) ----
    const int eb = (E + 255) / 256;
    cudaMemsetAsync(cntC, 0, C * sizeof(int));
    count_kernel<<<eb, 256>>>(c_edge, E, cntC);
    scan_reduce<<<SCAN_NB, 256>>>(cntC, C, bsC);
    scan_bsum<<<1, 256>>>(bsC);
    scan_write<<<SCAN_NB, 256>>>(cntC, C, bsC, rowC, E);
    cudaMemcpyAsync(curC, rowC, C * sizeof(int), cudaMemcpyDeviceToDevice);
    place_kernel<<<eb, 256>>>(c_edge, l_edge, E, curC, srcC);
    cudaMemsetAsync(cntL, 0, L * sizeof(int));
    count_kernel<<<eb, 256>>>(l_edge, E, cntL);
    scan_reduce<<<SCAN_NB, 256>>>(cntL, L, bsL);
    scan_bsum<<<1, 256>>>(bsL);
    scan_write<<<SCAN_NB, 256>>>(cntL, L, bsL, rowL, E);
    cudaMemcpyAsync(curL, rowL, L * sizeof(int), cudaMemcpyDeviceToDevice);
    place_kernel<<<eb, 256>>>(l_edge, c_edge, E, curL, srcL);

    const int ltiles = (L + 63) >> 6;
    const int ctiles = (C + 63) >> 6;
    auto gridFor = [](int tiles, int maxResident) {
        return tiles < maxResident ? tiles : maxResident;
    };
    const int g1L = gridFor(ltiles, 148 * 4);   // parts=1: ~56KB smem -> 4 blocks/SM
    const int g1C = gridFor(ctiles, 148 * 4);
    const int g2C = gridFor(ctiles, 148 * 3);   // parts=2: ~72KB -> 3 blocks/SM
    const int g3L = gridFor(ltiles, 148 * 2);   // parts=3: ~89KB -> 2 blocks/SM

    for (int t = 0; t < 2; ++t) {
        const float* le = outL + (size_t)t * L * DIM;
        const float* ce = outC + (size_t)t * C * DIM;
        float* nle = outL + (size_t)(t + 1) * L * DIM;
        float* nce = outC + (size_t)(t + 1) * C * DIM;

        // messages (from OLD embeddings)
        mlp_tc<1, false><<<g1L, 128, sm1>>>(le, nullptr, nullptr,
            W[0][0], W[0][1], W[0][2], W[0][3], Ml2c, L);
        mlp_tc<1, false><<<g1C, 128, sm1>>>(ce, nullptr, nullptr,
            W[1][0], W[1][1], W[1][2], W[1][3], Mc2l, C);
        mlp_tc<1, true><<<g1L, 128, sm1>>>(le, nullptr, nullptr,
            W[2][0], W[2][1], W[2][2], W[2][3], Ml2l, L);

        // aggregation via gather (no atomics, no memsets)
        gather_kernel<<<(C + 15) / 16, 256>>>(Ml2c, srcC, rowC, aggrC, C);
        gather_kernel<<<(L + 15) / 16, 256>>>(Mc2l, srcL, rowL, aggrL, L);

        // updates
        mlp_tc<2, false><<<g2C, 128, sm2>>>(ce, aggrC, nullptr,
            W[3][0], W[3][1], W[3][2], W[3][3], nce, C);
        mlp_tc<3, false><<<g3L, 128, sm3>>>(le, aggrL, Ml2l,
            W[4][0], W[4][1], W[4][2], W[4][3], nle, L);
    }
    (void)out_size;
}

// round 11
// speedup vs baseline: 1.3835x; 1.1122x over previous
#include <cuda_runtime.h>
#include <cuda_fp16.h>
#include <cstdint>

#define DIM 64
#define LMAX 200000
#define CMAX 80000
#define EMAX 1100000
#define SCAN_NB 256

// -------- scratch (static __device__ arrays; no allocation allowed) --------
__device__ float g_Ml2c[(size_t)LMAX * DIM];   // 51.2 MB
__device__ float g_Mc2l[(size_t)CMAX * DIM];   // 20.5 MB
__device__ float g_Ml2l[(size_t)LMAX * DIM];   // 51.2 MB
__device__ float g_aggrC[(size_t)CMAX * DIM];  // 20.5 MB
__device__ float g_aggrL[(size_t)LMAX * DIM];  // 51.2 MB
// CSR scratch
__device__ int g_cntC[CMAX],  g_rowC[CMAX + 1], g_curC[CMAX], g_srcC[EMAX];
__device__ int g_cntL[LMAX],  g_rowL[LMAX + 1], g_curL[LMAX], g_srcL[EMAX];
__device__ int g_bsumC[SCAN_NB], g_bsumL[SCAN_NB];

// ---------------------------------------------------------------------------
__device__ __forceinline__ void mma_16816(float* d, const uint32_t* a,
                                          const uint32_t* b)
{
    asm volatile(
        "mma.sync.aligned.m16n8k16.row.col.f32.f16.f16.f32 "
        "{%0,%1,%2,%3}, {%4,%5,%6,%7}, {%8,%9}, {%0,%1,%2,%3};\n"
        : "+f"(d[0]), "+f"(d[1]), "+f"(d[2]), "+f"(d[3])
        : "r"(a[0]), "r"(a[1]), "r"(a[2]), "r"(a[3]), "r"(b[0]), "r"(b[1]));
}

// ---------------------------------------------------------------------------
// Building blocks for the 2-term fp16-split MLP (validated R10: rel_err 1.2e-4)
// A (activations) single fp16; W staged as hi+lo fp16 pair -> one A-side
// rounding per GEMM. All smem strides are ==4 mod 32 words (conflict-free).
// ---------------------------------------------------------------------------
__device__ __forceinline__ void init_bias_frag(float a[2][4][4], const float* b,
                                               int wn, int tig)
{
    #pragma unroll
    for (int nt = 0; nt < 4; ++nt) {
        float bv0 = b[wn + nt * 8 + 2 * tig];
        float bv1 = b[wn + nt * 8 + 2 * tig + 1];
        #pragma unroll
        for (int mt = 0; mt < 2; ++mt) {
            a[mt][nt][0] = bv0; a[mt][nt][1] = bv1;
            a[mt][nt][2] = bv0; a[mt][nt][3] = bv1;
        }
    }
}

// acc += A[128x64 tile rows] @ (Wh+Wl)  over one 64-wide K segment
__device__ __forceinline__ void mma_accum_64(
    float acc[2][4][4],
    const __half* __restrict__ A,      // [128][72] halves
    const __half* __restrict__ Wh, const __half* __restrict__ Wl,
    int wstride, int koff,
    int wm, int wn, int gid, int tig)
{
    #pragma unroll
    for (int kb = 0; kb < 4; ++kb) {
        const int k0 = kb * 16;
        uint32_t ah[2][4];
        #pragma unroll
        for (int mt = 0; mt < 2; ++mt) {
            int r0 = (wm + mt * 16 + gid) * 72;
            int r8 = r0 + 8 * 72;
            ah[mt][0] = *(const uint32_t*)(A + r0 + k0 + 2 * tig);
            ah[mt][1] = *(const uint32_t*)(A + r8 + k0 + 2 * tig);
            ah[mt][2] = *(const uint32_t*)(A + r0 + k0 + 2 * tig + 8);
            ah[mt][3] = *(const uint32_t*)(A + r8 + k0 + 2 * tig + 8);
        }
        uint32_t bh[4][2], bl[4][2];
        #pragma unroll
        for (int nt = 0; nt < 4; ++nt) {
            int n = (wn + nt * 8 + gid) * wstride + koff + k0;
            bh[nt][0] = *(const uint32_t*)(Wh + n + 2 * tig);
            bh[nt][1] = *(const uint32_t*)(Wh + n + 2 * tig + 8);
            bl[nt][0] = *(const uint32_t*)(Wl + n + 2 * tig);
            bl[nt][1] = *(const uint32_t*)(Wl + n + 2 * tig + 8);
        }
        #pragma unroll
        for (int nt = 0; nt < 4; ++nt) {
            mma_16816(acc[0][nt], ah[0], bh[nt]);
            mma_16816(acc[1][nt], ah[1], bh[nt]);
        }
        #pragma unroll
        for (int nt = 0; nt < 4; ++nt) {
            mma_16816(acc[0][nt], ah[0], bl[nt]);
            mma_16816(acc[1][nt], ah[1], bl[nt]);
        }
    }
}

__device__ __forceinline__ void relu_to_smem(const float a[2][4][4], __half* Hs,
                                             int wm, int wn, int gid, int tig)
{
    #pragma unroll
    for (int mt = 0; mt < 2; ++mt)
        #pragma unroll
        for (int nt = 0; nt < 4; ++nt) {
            int r0 = wm + mt * 16 + gid;
            int c0 = wn + nt * 8 + 2 * tig;
            *(__half2*)(Hs + r0 * 72 + c0) =
                __floats2half2_rn(fmaxf(a[mt][nt][0], 0.f), fmaxf(a[mt][nt][1], 0.f));
            *(__half2*)(Hs + (r0 + 8) * 72 + c0) =
                __floats2half2_rn(fmaxf(a[mt][nt][2], 0.f), fmaxf(a[mt][nt][3], 0.f));
        }
}

__device__ __forceinline__ void epilogue_store(const float o[2][4][4], float* out,
                                               int base, int nrows, bool flip,
                                               int wm, int wn, int gid, int tig)
{
    #pragma unroll
    for (int mt = 0; mt < 2; ++mt)
        #pragma unroll
        for (int nt = 0; nt < 4; ++nt) {
            int r = base + wm + mt * 16 + gid;
            int c = wn + nt * 8 + 2 * tig;
            if (r < nrows) {
                int ro = flip ? (r ^ 1) : r;
                *(float2*)(out + (size_t)ro * 64 + c) =
                    make_float2(o[mt][nt][0], o[mt][nt][1]);
            }
            if (r + 8 < nrows) {
                int ro = flip ? ((r + 8) ^ 1) : (r + 8);
                *(float2*)(out + (size_t)ro * 64 + c) =
                    make_float2(o[mt][nt][2], o[mt][nt][3]);
            }
        }
}

// ---------------------------------------------------------------------------
// 2-term fp16-split MLP, 128-row tiles, 256 threads (8 warps, 4m x 2n of
// 32x32 quadrants), register-prefetch pipeline on X staging.
// FUSE: run a second MLP (weights b) on the SAME staged X, second output
// written pair-flipped (row r -> r^1) == l2l semantics.
// ---------------------------------------------------------------------------
template <int PARTS, bool FUSE>
__global__ __launch_bounds__(256, 2) void mlp_tc(
    const float* __restrict__ x0, const float* __restrict__ x1,
    const float* __restrict__ x2,
    const float* __restrict__ W1a, const float* __restrict__ b1a,
    const float* __restrict__ W2a, const float* __restrict__ b2a,
    float* __restrict__ outA,
    const float* __restrict__ W1b, const float* __restrict__ b1b,
    const float* __restrict__ W2b, const float* __restrict__ b2b,
    float* __restrict__ outB,
    int nrows)
{
    constexpr int K  = PARTS * 64;
    constexpr int WS = K + 8;

    extern __shared__ __half smh[];
    __half* W1ah = smh;                       // [64][WS]
    __half* W1al = W1ah + 64 * WS;
    __half* W2ah = W1al + 64 * WS;            // [64][72]
    __half* W2al = W2ah + 64 * 72;
    __half* W1bh = W2al + 64 * 72;            // FUSE only (K=64, stride 72)
    __half* W1bl = W1bh + (FUSE ? 64 * 72 : 0);
    __half* W2bh = W1bl + (FUSE ? 64 * 72 : 0);
    __half* W2bl = W2bh + (FUSE ? 64 * 72 : 0);
    __half* Xs   = W2bl + (FUSE ? 64 * 72 : 0);   // [128][72]
    __half* Hs   = Xs + 128 * 72;                 // [128][72]
    float*  bias = (float*)(Hs + 128 * 72);       // b1a,b2a[,b1b,b2b] x64

    const int tid = threadIdx.x;
    // stage weights transposed (n-major), hi/lo split
    for (int i = tid; i < K * 64; i += 256) {
        int k = i >> 6, n = i & 63;
        float w = W1a[i];
        __half hi = __float2half_rn(w);
        W1ah[n * WS + k] = hi;
        W1al[n * WS + k] = __float2half_rn(w - __half2float(hi));
    }
    for (int i = tid; i < 64 * 64; i += 256) {
        int k = i >> 6, n = i & 63;
        float w = W2a[i];
        __half hi = __float2half_rn(w);
        W2ah[n * 72 + k] = hi;
        W2al[n * 72 + k] = __float2half_rn(w - __half2float(hi));
    }
    if (FUSE) {
        for (int i = tid; i < 64 * 64; i += 256) {
            int k = i >> 6, n = i & 63;
            float w = W1b[i];
            __half hi = __float2half_rn(w);
            W1bh[n * 72 + k] = hi;
            W1bl[n * 72 + k] = __float2half_rn(w - __half2float(hi));
            float w2 = W2b[i];
            __half h2 = __float2half_rn(w2);
            W2bh[n * 72 + k] = h2;
            W2bl[n * 72 + k] = __float2half_rn(w2 - __half2float(h2));
        }
    }
    if (tid < 64) {
        bias[tid] = b1a[tid]; bias[64 + tid] = b2a[tid];
        if (FUSE) { bias[128 + tid] = b1b[tid]; bias[192 + tid] = b2b[tid]; }
    }
    __syncthreads();   // weights+bias visible to all warps (R3/R4 lesson)

    const int lane = tid & 31;
    const int warp = tid >> 5;
    const int gid = lane >> 2, tig = lane & 3;
    const int wm = (warp & 3) * 32;   // 4 m-quadrants over 128 rows
    const int wn = (warp >> 2) * 32;  // 2 n-quadrants over 64 cols

    const int ntiles = (nrows + 127) >> 7;
    int tile = blockIdx.x;
    float2 pf[16];
    if (tile < ntiles) {   // prologue prefetch: (tile, part 0)
        #pragma unroll
        for (int i = 0; i < 16; ++i) {
            int idx = tid + i * 256;
            int r = idx >> 5, kp = idx & 31;
            int row = (tile << 7) + r;
            pf[i] = (row < nrows) ? *(const float2*)(x0 + (size_t)row * 64 + 2 * kp)
                                  : make_float2(0.f, 0.f);
        }
    }

    for (; tile < ntiles; tile += gridDim.x) {
        const int base = tile << 7;
        float acc[2][4][4];
        init_bias_frag(acc, bias, wn, tig);

        #pragma unroll
        for (int p = 0; p < PARTS; ++p) {
            __syncthreads();   // Xs (and Hs via barrier transitivity) reusable
            #pragma unroll
            for (int i = 0; i < 16; ++i) {
                int idx = tid + i * 256;
                int r = idx >> 5, kp = idx & 31;
                *(__half2*)(Xs + r * 72 + 2 * kp) = __floats2half2_rn(pf[i].x, pf[i].y);
            }
            __syncthreads();
            // prefetch next stage while MMAs run (hides gmem latency)
            int np = p + 1;
            int ntile = tile;
            if (np == PARTS) { np = 0; ntile = tile + (int)gridDim.x; }
            if (ntile < ntiles) {
                const float* nx = (np == 0) ? x0 : ((np == 1) ? x1 : x2);
                int nb = ntile << 7;
                #pragma unroll
                for (int i = 0; i < 16; ++i) {
                    int idx = tid + i * 256;
                    int r = idx >> 5, kp = idx & 31;
                    int row = nb + r;
                    pf[i] = (row < nrows)
                          ? *(const float2*)(nx + (size_t)row * 64 + 2 * kp)
                          : make_float2(0.f, 0.f);
                }
            }
            mma_accum_64(acc, Xs, W1ah, W1al, WS, p * 64, wm, wn, gid, tig);
        }

        relu_to_smem(acc, Hs, wm, wn, gid, tig);
        __syncthreads();
        float o[2][4][4];
        init_bias_frag(o, bias + 64, wn, tig);
        mma_accum_64(o, Hs, W2ah, W2al, 72, 0, wm, wn, gid, tig);
        epilogue_store(o, outA, base, nrows, false, wm, wn, gid, tig);

        if (FUSE) {
            __syncthreads();   // all warps done reading Hs before it is rewritten
            float acc2[2][4][4];
            init_bias_frag(acc2, bias + 128, wn, tig);
            mma_accum_64(acc2, Xs, W1bh, W1bl, 72, 0, wm, wn, gid, tig);
            relu_to_smem(acc2, Hs, wm, wn, gid, tig);
            __syncthreads();
            float o2[2][4][4];
            init_bias_frag(o2, bias + 192, wn, tig);
            mma_accum_64(o2, Hs, W2bh, W2bl, 72, 0, wm, wn, gid, tig);
            epilogue_store(o2, outB, base, nrows, true, wm, wn, gid, tig);
        }
    }
}

// ---------------------------------------------------------------------------
// CSR build: count -> 3-kernel exclusive scan -> atomic placement
// ---------------------------------------------------------------------------
__global__ void count_kernel(const int* __restrict__ dest, int E, int* __restrict__ cnt)
{
    int e = blockIdx.x * 256 + threadIdx.x;
    if (e < E) atomicAdd(&cnt[dest[e]], 1);
}

__global__ void scan_reduce(const int* __restrict__ cnt, int n, int* __restrict__ bsum)
{
    int b = blockIdx.x;
    int CH = (n + SCAN_NB - 1) / SCAN_NB;
    int s = b * CH, e = min(n, s + CH);
    __shared__ int sh[256];
    int t = threadIdx.x, sum = 0;
    for (int i = s + t; i < e; i += 256) sum += cnt[i];
    sh[t] = sum; __syncthreads();
    for (int o = 128; o > 0; o >>= 1) {
        if (t < o) sh[t] += sh[t + o];
        __syncthreads();
    }
    if (t == 0) bsum[b] = sh[0];
}

__global__ void scan_bsum(int* __restrict__ bsum)
{
    __shared__ int sh[256];
    int t = threadIdx.x;
    sh[t] = bsum[t]; __syncthreads();
    for (int o = 1; o < 256; o <<= 1) {
        int v = (t >= o) ? sh[t - o] : 0;
        __syncthreads();
        sh[t] += v;
        __syncthreads();
    }
    bsum[t] = (t == 0) ? 0 : sh[t - 1];
}

__global__ void scan_write(const int* __restrict__ cnt, int n,
                           const int* __restrict__ bsum, int* __restrict__ rowptr, int total)
{
    int b = blockIdx.x;
    int CH = (n + SCAN_NB - 1) / SCAN_NB;
    int s = b * CH, e = min(n, s + CH);
    int t = threadIdx.x;
    int per = (CH + 255) / 256;
    int ts = min(e, s + t * per), te = min(e, s + t * per + per);
    int sum = 0;
    for (int i = ts; i < te; ++i) sum += cnt[i];
    __shared__ int sh[256];
    sh[t] = sum; __syncthreads();
    for (int o = 1; o < 256; o <<= 1) {
        int v = (t >= o) ? sh[t - o] : 0;
        __syncthreads();
        sh[t] += v;
        __syncthreads();
    }
    int off = bsum[b] + ((t == 0) ? 0 : sh[t - 1]);
    for (int i = ts; i < te; ++i) { rowptr[i] = off; off += cnt[i]; }
    if (b == 0 && t == 0) rowptr[n] = total;
}

__global__ void place_kernel(const int* __restrict__ dest, const int* __restrict__ srcn,
                             int E, int* __restrict__ cursor, int* __restrict__ srcidx)
{
    int e = blockIdx.x * 256 + threadIdx.x;
    if (e < E) {
        int p = atomicAdd(&cursor[dest[e]], 1);
        srcidx[p] = srcn[e];
    }
}

// ---------------------------------------------------------------------------
// Gather aggregation: dst[d] = sum over CSR row d of src[srcidx[i]]  (64 floats)
// ---------------------------------------------------------------------------
__global__ __launch_bounds__(256) void gather_kernel(
    const float* __restrict__ src, const int* __restrict__ srcidx,
    const int* __restrict__ rowptr, float* __restrict__ dst, int n)
{
    int d = blockIdx.x * 16 + (threadIdx.x >> 4);
    int q = threadIdx.x & 15;
    if (d >= n) return;
    int s = rowptr[d], e = rowptr[d + 1];
    float ax = 0.f, ay = 0.f, az = 0.f, aw = 0.f;
    for (int i = s; i < e; ++i) {
        int r = __ldg(srcidx + i);
        float4 v = *(const float4*)(src + (size_t)r * 64 + q * 4);
        ax += v.x; ay += v.y; az += v.z; aw += v.w;
    }
    *(float4*)(dst + (size_t)d * 64 + q * 4) = make_float4(ax, ay, az, aw);
}

// ---------------------------------------------------------------------------
static inline size_t mlp_smem_bytes(int parts, bool fuse)
{
    size_t WS = parts * 64 + 8;
    size_t halves = 2 * 64 * WS + 2 * 64 * 72 + (fuse ? 4 * 64 * 72 : 0)
                  + (size_t)2 * 128 * 72;
    return halves * 2 + 256 * sizeof(float);
}

extern "C" void kernel_launch(void* const* d_in, const int* in_sizes, int n_in,
                              void* d_out, int out_size)
{
    const int off = n_in - 24;
    const int* l_edge = (const int*)d_in[off + 0];
    const int* c_edge = (const int*)d_in[off + 1];
    const float* l_emb_in = (const float*)d_in[off + 2];
    const float* c_emb_in = (const float*)d_in[off + 3];
    const int E = in_sizes[off + 0];
    const int L = in_sizes[off + 2] / DIM;
    const int C = in_sizes[off + 3] / DIM;

    const float* W[5][4];
    for (int m = 0; m < 5; ++m)
        for (int j = 0; j < 4; ++j)
            W[m][j] = (const float*)d_in[off + 4 + m * 4 + j];
    // m: 0=l2c, 1=c2l, 2=l2l, 3=cu, 4=lu

    float* Ml2c, * Mc2l, * Ml2l, * aggrC, * aggrL;
    int *cntC, *rowC, *curC, *srcC, *bsC;
    int *cntL, *rowL, *curL, *srcL, *bsL;
    cudaGetSymbolAddress((void**)&Ml2c, g_Ml2c);
    cudaGetSymbolAddress((void**)&Mc2l, g_Mc2l);
    cudaGetSymbolAddress((void**)&Ml2l, g_Ml2l);
    cudaGetSymbolAddress((void**)&aggrC, g_aggrC);
    cudaGetSymbolAddress((void**)&aggrL, g_aggrL);
    cudaGetSymbolAddress((void**)&cntC, g_cntC);
    cudaGetSymbolAddress((void**)&rowC, g_rowC);
    cudaGetSymbolAddress((void**)&curC, g_curC);
    cudaGetSymbolAddress((void**)&srcC, g_srcC);
    cudaGetSymbolAddress((void**)&bsC,  g_bsumC);
    cudaGetSymbolAddress((void**)&cntL, g_cntL);
    cudaGetSymbolAddress((void**)&rowL, g_rowL);
    cudaGetSymbolAddress((void**)&curL, g_curL);
    cudaGetSymbolAddress((void**)&srcL, g_srcL);
    cudaGetSymbolAddress((void**)&bsL,  g_bsumL);

    const size_t smF = mlp_smem_bytes(1, true);
    const size_t sm1 = mlp_smem_bytes(1, false);
    const size_t sm2 = mlp_smem_bytes(2, false);
    const size_t sm3 = mlp_smem_bytes(3, false);
    cudaFuncSetAttribute(mlp_tc<1, true>,  cudaFuncAttributeMaxDynamicSharedMemorySize, (int)smF);
    cudaFuncSetAttribute(mlp_tc<1, false>, cudaFuncAttributeMaxDynamicSharedMemorySize, (int)sm1);
    cudaFuncSetAttribute(mlp_tc<2, false>, cudaFuncAttributeMaxDynamicSharedMemorySize, (int)sm2);
    cudaFuncSetAttribute(mlp_tc<3, false>, cudaFuncAttributeMaxDynamicSharedMemorySize, (int)sm3);

    float* outBase = (float*)d_out;
    float* outL = outBase;                          // (3, L, 64)
    float* outC = outBase + (size_t)3 * L * DIM;    // (3, C, 64)

    cudaMemcpyAsync(outL, l_emb_in, (size_t)L * DIM * sizeof(float), cudaMemcpyDeviceToDevice);
    cudaMemcpyAsync(outC, c_emb_in, (size_t)C * DIM * sizeof(float), cudaMemcpyDeviceToDevice);

    // ---- CSR build (edges are iteration-invariant; amortized over 4 gathers) ----
    const int eb = (E + 255) / 256;
    cudaMemsetAsync(cntC, 0, C * sizeof(int));
    count_kernel<<<eb, 256>>>(c_edge, E, cntC);
    scan_reduce<<<SCAN_NB, 256>>>(cntC, C, bsC);
    scan_bsum<<<1, 256>>>(bsC);
    scan_write<<<SCAN_NB, 256>>>(cntC, C, bsC, rowC, E);
    cudaMemcpyAsync(curC, rowC, C * sizeof(int), cudaMemcpyDeviceToDevice);
    place_kernel<<<eb, 256>>>(c_edge, l_edge, E, curC, srcC);
    cudaMemsetAsync(cntL, 0, L * sizeof(int));
    count_kernel<<<eb, 256>>>(l_edge, E, cntL);
    scan_reduce<<<SCAN_NB, 256>>>(cntL, L, bsL);
    scan_bsum<<<1, 256>>>(bsL);
    scan_write<<<SCAN_NB, 256>>>(cntL, L, bsL, rowL, E);
    cudaMemcpyAsync(curL, rowL, L * sizeof(int), cudaMemcpyDeviceToDevice);
    place_kernel<<<eb, 256>>>(l_edge, c_edge, E, curL, srcL);

    const int ltiles = (L + 127) >> 7;
    const int ctiles = (C + 127) >> 7;
    auto gridFor = [](int tiles, int maxResident) {
        return tiles < maxResident ? tiles : maxResident;
    };
    const int gF  = gridFor(ltiles, 148 * 2);
    const int g1C = gridFor(ctiles, 148 * 2);
    const int g2C = gridFor(ctiles, 148 * 2);
    const int g3L = gridFor(ltiles, 148 * 2);

    for (int t = 0; t < 2; ++t) {
        const float* le = outL + (size_t)t * L * DIM;
        const float* ce = outC + (size_t)t * C * DIM;
        float* nle = outL + (size_t)(t + 1) * L * DIM;
        float* nce = outC + (size_t)(t + 1) * C * DIM;

        // fused messages from le: l2c (plain) + l2l (flipped output)
        mlp_tc<1, true><<<gF, 256, smF>>>(le, nullptr, nullptr,
            W[0][0], W[0][1], W[0][2], W[0][3], Ml2c,
            W[2][0], W[2][1], W[2][2], W[2][3], Ml2l, L);
        // c2l from ce
        mlp_tc<1, false><<<g1C, 256, sm1>>>(ce, nullptr, nullptr,
            W[1][0], W[1][1], W[1][2], W[1][3], Mc2l,
            nullptr, nullptr, nullptr, nullptr, nullptr, C);

        // aggregation via gather (no atomics, no memsets)
        gather_kernel<<<(C + 15) / 16, 256>>>(Ml2c, srcC, rowC, aggrC, C);
        gather_kernel<<<(L + 15) / 16, 256>>>(Mc2l, srcL, rowL, aggrL, L);

        // updates
        mlp_tc<2, false><<<g2C, 256, sm2>>>(ce, aggrC, nullptr,
            W[3][0], W[3][1], W[3][2], W[3][3], nce,
            nullptr, nullptr, nullptr, nullptr, nullptr, C);
        mlp_tc<3, false><<<g3L, 256, sm3>>>(le, aggrL, Ml2l,
            W[4][0], W[4][1], W[4][2], W[4][3], nle,
            nullptr, nullptr, nullptr, nullptr, nullptr, L);
    }
    (void)out_size;
}